// round 4
// baseline (speedup 1.0000x reference)
#include <cuda_runtime.h>
#include <cstdint>

#define NODES 100000
#define EDGES 1600000
#define TILES 782            // 782 * 128 = 100096
#define NPAD  100096
#define CHUNK 1024
#define NCHUNK 98

// ---------------- scratch (device globals; no allocation) ----------------
__device__ int   d_deg[NODES];
__device__ int   d_cursor[NODES];
__device__ int   d_row[NODES + 1];
__device__ int   d_csr[EDGES];
__device__ int   d_csums[NCHUNK];
__device__ float d_mean1[NPAD * 128];   // mean-aggregated x (padded rows stay 0)
__device__ float d_pl[NPAD * 64];       // h1 @ W2l^T (to be aggregated)
__device__ float d_pr[NPAD * 64];       // h1 @ W2r^T (self term)
__device__ float d_wt1[256 * 128];      // transposed [W1l; W1r]  (k-major)
__device__ float d_wt2[128 * 128];      // transposed [W2l | W2r] (k-major)

// ---------------- helpers ----------------
__device__ __forceinline__ uint32_t f2tf(float f) {
    uint32_t u; asm("cvt.rna.tf32.f32 %0, %1;" : "=r"(u) : "f"(f)); return u;
}

__device__ __forceinline__ void mma8(float* d, const uint32_t* a, uint2 b) {
    asm volatile(
        "mma.sync.aligned.m16n8k8.row.col.f32.tf32.tf32.f32 "
        "{%0,%1,%2,%3}, {%4,%5,%6,%7}, {%8,%9}, {%0,%1,%2,%3};\n"
        : "+f"(d[0]), "+f"(d[1]), "+f"(d[2]), "+f"(d[3])
        : "r"(a[0]), "r"(a[1]), "r"(a[2]), "r"(a[3]), "r"(b.x), "r"(b.y));
}

// ---------------- CSR build ----------------
__global__ void k_zero() {
    int i = blockIdx.x * blockDim.x + threadIdx.x;
    if (i < NODES) { d_deg[i] = 0; d_cursor[i] = 0; }
}

__global__ void k_hist(const int* __restrict__ dst) {
    int i = blockIdx.x * blockDim.x + threadIdx.x;
    if (i < EDGES) atomicAdd(&d_deg[dst[i]], 1);
}

__global__ void k_scan1() {
    __shared__ int ws[32];
    int i = blockIdx.x * CHUNK + threadIdx.x;
    int lane = threadIdx.x & 31, wid = threadIdx.x >> 5;
    int v = (i < NODES) ? d_deg[i] : 0;
    int x = v;
    #pragma unroll
    for (int o = 1; o < 32; o <<= 1) {
        int y = __shfl_up_sync(0xffffffffu, x, o);
        if (lane >= o) x += y;
    }
    if (lane == 31) ws[wid] = x;
    __syncthreads();
    if (wid == 0) {
        int s = ws[lane];
        #pragma unroll
        for (int o = 1; o < 32; o <<= 1) {
            int y = __shfl_up_sync(0xffffffffu, s, o);
            if (lane >= o) s += y;
        }
        ws[lane] = s;
    }
    __syncthreads();
    int incl = x + (wid > 0 ? ws[wid - 1] : 0);
    if (i < NODES) d_row[i] = incl - v;
    if (threadIdx.x == CHUNK - 1) d_csums[blockIdx.x] = incl;
}

__global__ void k_scan2() {   // 128-thread parallel scan over NCHUNK
    __shared__ int ws[4];
    int t = threadIdx.x, lane = t & 31, w = t >> 5;
    int v = (t < NCHUNK) ? d_csums[t] : 0;
    int xx = v;
    #pragma unroll
    for (int o = 1; o < 32; o <<= 1) {
        int y = __shfl_up_sync(0xffffffffu, xx, o);
        if (lane >= o) xx += y;
    }
    if (lane == 31) ws[w] = xx;
    __syncthreads();
    int add = 0;
    #pragma unroll
    for (int i = 0; i < 4; i++) add += (i < w) ? ws[i] : 0;
    if (t < NCHUNK) d_csums[t] = xx + add - v;
}

__global__ void k_scan3() {
    int i = blockIdx.x * blockDim.x + threadIdx.x;
    if (i < NODES) d_row[i] += d_csums[i / CHUNK];
    if (i == 0) d_row[NODES] = EDGES;
}

__global__ void k_scatter(const int* __restrict__ src, const int* __restrict__ dst) {
    int i = blockIdx.x * blockDim.x + threadIdx.x;
    if (i < EDGES) {
        int d = dst[i];
        int o = atomicAdd(&d_cursor[d], 1);
        d_csr[d_row[d] + o] = src[i];
    }
}

// ---------------- weight pre-transpose ----------------
__global__ void k_wt(const float* __restrict__ W1l, const float* __restrict__ W1r,
                     const float* __restrict__ W2l, const float* __restrict__ W2r) {
    int i = blockIdx.x * blockDim.x + threadIdx.x;
    if (i < 256 * 128) {
        int k = i >> 7, n = i & 127;
        d_wt1[i] = (k < 128) ? W1l[n * 128 + k] : W1r[n * 128 + (k - 128)];
    }
    if (i < 128 * 128) {
        int k = i >> 7, n = i & 127;
        d_wt2[i] = (n < 64) ? W2l[n * 128 + k] : W2r[(n - 64) * 128 + k];
    }
}

// ---------------- layer1 aggregation: warp per node ----------------
__global__ void __launch_bounds__(256) k_agg1(const float* __restrict__ x) {
    int gw = (blockIdx.x * blockDim.x + threadIdx.x) >> 5;
    int lane = threadIdx.x & 31;
    if (gw >= NODES) return;
    int s0 = d_row[gw], s1 = d_row[gw + 1];
    const float4* x4 = (const float4*)x;
    float4 acc = make_float4(0.f, 0.f, 0.f, 0.f);
    for (int base = s0; base < s1; base += 32) {
        int rem = s1 - base;
        int sv = (lane < rem) ? d_csr[base + lane] : 0;
        int cnt = rem < 32 ? rem : 32;
        int j = 0;
        for (; j + 4 <= cnt; j += 4) {
            int sa = __shfl_sync(0xffffffffu, sv, j);
            int sb = __shfl_sync(0xffffffffu, sv, j + 1);
            int sc = __shfl_sync(0xffffffffu, sv, j + 2);
            int sd = __shfl_sync(0xffffffffu, sv, j + 3);
            float4 va = x4[sa * 32 + lane];
            float4 vb = x4[sb * 32 + lane];
            float4 vc = x4[sc * 32 + lane];
            float4 vd = x4[sd * 32 + lane];
            acc.x += va.x + vb.x + vc.x + vd.x;
            acc.y += va.y + vb.y + vc.y + vd.y;
            acc.z += va.z + vb.z + vc.z + vd.z;
            acc.w += va.w + vb.w + vc.w + vd.w;
        }
        for (; j < cnt; j++) {
            int s = __shfl_sync(0xffffffffu, sv, j);
            float4 v = x4[s * 32 + lane];
            acc.x += v.x; acc.y += v.y; acc.z += v.z; acc.w += v.w;
        }
    }
    int deg = s1 - s0;
    float sc = 1.0f / (float)(deg > 1 ? deg : 1);
    float4 m = make_float4(acc.x * sc, acc.y * sc, acc.z * sc, acc.w * sc);
    ((float4*)d_mean1)[gw * 32 + lane] = m;
}

// ---------------- fused TF32 mma.sync GEMM: layer1 + layer2 projections ----------------
// Per tile (128 nodes): acc1 = [mean1|x] @ wt1 (K=256); epilogue1 = bias+relu
// restaged from registers into the A-buffer chunk-by-chunk; acc2 = h1 @ wt2
// (K=128); epilogue2 -> d_pl/d_pr. h1 never touches gmem.
// smem words: Bp1 32768 @0, Bp2 16384 @32768, Ab 2*4096 @49152.  Total 229376 B.
extern __shared__ uint32_t smu[];

__global__ void __launch_bounds__(256) k_fused(const float* __restrict__ x,
                                               const float* __restrict__ b1) {
    uint32_t* Bp1 = smu;
    uint32_t* Bp2 = smu + 32768;
    uint32_t* Ab  = smu + 49152;
    int tid = threadIdx.x, lane = tid & 31, w = tid >> 5;
    int wr = w >> 1, wc = w & 1;
    int g = lane >> 2, t = lane & 3;

    for (int i = tid; i < 32768; i += 256) {
        int k = i >> 7, n = i & 127;
        int ks = k >> 3, r = k & 7, half = r >> 2, lk = r & 3;
        Bp1[((ks * 128 + n) << 3) + (lk << 1) + half] = f2tf(d_wt1[i]);
    }
    for (int i = tid; i < 16384; i += 256) {
        int k = i >> 7, n = i & 127;
        int ks = k >> 3, r = k & 7, half = r >> 2, lk = r & 3;
        Bp2[((ks * 128 + n) << 3) + (lk << 1) + half] = f2tf(d_wt2[i]);
    }
    __syncthreads();

    int arow = tid >> 1;             // 0..127
    int acol0 = (tid & 1) << 4;      // 0 or 16

    // bias for this thread's columns (tile-invariant)
    float bx[8], by[8];
    #pragma unroll
    for (int nf = 0; nf < 8; nf++) {
        int cc = wc * 64 + nf * 8 + 2 * t;
        bx[nf] = b1[cc]; by[nf] = b1[cc + 1];
    }

    for (int tile = blockIdx.x; tile < TILES; tile += gridDim.x) {
        int nb = tile << 7;

        // ======== GEMM1: acc1 = [mean1 | x] @ wt1, K=256 (8 chunks) ========
        float acc1[2][8][4];
        #pragma unroll
        for (int mf = 0; mf < 2; mf++)
            #pragma unroll
            for (int nf = 0; nf < 8; nf++)
                #pragma unroll
                for (int q = 0; q < 4; q++) acc1[mf][nf][q] = 0.f;

        float4 r4[4];
        auto ldgch = [&](int c) {
            int node = nb + arow;
            const float* src;
            if (c < 4) src = d_mean1 + (size_t)node * 128 + c * 32 + acol0;
            else {
                int nc = node < NODES ? node : NODES - 1;
                src = x + (size_t)nc * 128 + (c - 4) * 32 + acol0;
            }
            #pragma unroll
            for (int i = 0; i < 4; i++) r4[i] = *(const float4*)(src + 4 * i);
        };
        auto stsch = [&](int buf) {
            #pragma unroll
            for (int i = 0; i < 4; i++) {
                int cc = acol0 + 4 * i;
                int ks = cc >> 3, kloc = cc & 7;
                uint32_t* p = Ab + buf * 4096 + ks * 1024 + arow * 8 + kloc;
                *(uint4*)p = make_uint4(f2tf(r4[i].x), f2tf(r4[i].y),
                                        f2tf(r4[i].z), f2tf(r4[i].w));
            }
        };

        ldgch(0);
        #pragma unroll 1
        for (int c = 0; c < 8; c++) {
            int buf = c & 1;
            stsch(buf);
            __syncthreads();
            if (c < 7) ldgch(c + 1);
            const uint32_t* abase0 = Ab + buf * 4096;
            #pragma unroll
            for (int ks = 0; ks < 4; ks++) {
                const uint32_t* ab = abase0 + ks * 1024;
                uint32_t a[2][4];
                #pragma unroll
                for (int mf = 0; mf < 2; mf++) {
                    int r0 = wr * 32 + mf * 16 + g;
                    a[mf][0] = ab[r0 * 8 + t];
                    a[mf][1] = ab[(r0 + 8) * 8 + t];
                    a[mf][2] = ab[r0 * 8 + t + 4];
                    a[mf][3] = ab[(r0 + 8) * 8 + t + 4];
                }
                int ksg = c * 4 + ks;
                #pragma unroll
                for (int nf = 0; nf < 8; nf++) {
                    int n = wc * 64 + nf * 8 + g;
                    uint2 b = *(const uint2*)(Bp1 + ((ksg * 128 + n) << 3) + (t << 1));
                    mma8(acc1[0][nf], a[0], b);
                    mma8(acc1[1][nf], a[1], b);
                }
            }
        }
        __syncthreads();   // all GEMM1 mma reads of Ab done before h1 restage

        // ======== GEMM2: acc2 = relu(acc1 + b1) @ wt2, K=128 (4 chunks) ========
        // h1 column cc = wc*64 + nf*8 + 2t(+1) belongs to k-chunk c = cc>>5:
        //   wc=0,nf<4 -> c0; wc=0,nf>=4 -> c1; wc=1,nf<4 -> c2; wc=1,nf>=4 -> c3.
        // Within the chunk: ks = nf&3, kloc = 2t(,+1).
        float acc2[2][8][4];
        #pragma unroll
        for (int mf = 0; mf < 2; mf++)
            #pragma unroll
            for (int nf = 0; nf < 8; nf++)
                #pragma unroll
                for (int q = 0; q < 4; q++) acc2[mf][nf][q] = 0.f;

        #pragma unroll 1
        for (int c = 0; c < 4; c++) {
            int buf = c & 1;
            if (wc == (c >> 1)) {
                #pragma unroll
                for (int mf = 0; mf < 2; mf++) {
                    #pragma unroll
                    for (int nfl = 0; nfl < 4; nfl++) {
                        int nf = (c & 1) * 4 + nfl;
                        float v0 = fmaxf(acc1[mf][nf][0] + bx[nf], 0.f);
                        float v1 = fmaxf(acc1[mf][nf][1] + by[nf], 0.f);
                        float v2 = fmaxf(acc1[mf][nf][2] + bx[nf], 0.f);
                        float v3 = fmaxf(acc1[mf][nf][3] + by[nf], 0.f);
                        int r0 = wr * 32 + mf * 16 + g;
                        uint32_t* pb = Ab + buf * 4096 + nfl * 1024;
                        *(uint2*)(pb + r0 * 8 + 2 * t)       = make_uint2(f2tf(v0), f2tf(v1));
                        *(uint2*)(pb + (r0 + 8) * 8 + 2 * t) = make_uint2(f2tf(v2), f2tf(v3));
                    }
                }
            }
            __syncthreads();
            const uint32_t* abase0 = Ab + buf * 4096;
            #pragma unroll
            for (int ks = 0; ks < 4; ks++) {
                const uint32_t* ab = abase0 + ks * 1024;
                uint32_t a[2][4];
                #pragma unroll
                for (int mf = 0; mf < 2; mf++) {
                    int r0 = wr * 32 + mf * 16 + g;
                    a[mf][0] = ab[r0 * 8 + t];
                    a[mf][1] = ab[(r0 + 8) * 8 + t];
                    a[mf][2] = ab[r0 * 8 + t + 4];
                    a[mf][3] = ab[(r0 + 8) * 8 + t + 4];
                }
                int ksg = c * 4 + ks;
                #pragma unroll
                for (int nf = 0; nf < 8; nf++) {
                    int n = wc * 64 + nf * 8 + g;
                    uint2 b = *(const uint2*)(Bp2 + ((ksg * 128 + n) << 3) + (t << 1));
                    mma8(acc2[0][nf], a[0], b);
                    mma8(acc2[1][nf], a[1], b);
                }
            }
        }

        // ======== epilogue2: acc2 -> d_pl / d_pr ========
        #pragma unroll
        for (int mf = 0; mf < 2; mf++) {
            int r0 = nb + wr * 32 + mf * 16 + g;
            #pragma unroll
            for (int nf = 0; nf < 8; nf++) {
                int cc = wc * 64 + nf * 8 + 2 * t;
                float2 v0 = { acc2[mf][nf][0], acc2[mf][nf][1] };
                float2 v1 = { acc2[mf][nf][2], acc2[mf][nf][3] };
                if (wc == 0) {
                    *(float2*)(d_pl + (size_t)r0 * 64 + cc) = v0;
                    *(float2*)(d_pl + (size_t)(r0 + 8) * 64 + cc) = v1;
                } else {
                    *(float2*)(d_pr + (size_t)r0 * 64 + (cc - 64)) = v0;
                    *(float2*)(d_pr + (size_t)(r0 + 8) * 64 + (cc - 64)) = v1;
                }
            }
        }
        __syncthreads();
    }
}

// ---------------- layer2 aggregation + bias + relu + FC, fused ----------------
__global__ void __launch_bounds__(256) k_agg2fc(const float* __restrict__ b2,
                                                const float* __restrict__ Wfc,
                                                const float* __restrict__ bfc,
                                                float* __restrict__ out) {
    int gw = (blockIdx.x * blockDim.x + threadIdx.x) >> 5;
    int lane = threadIdx.x & 31;
    if (gw >= NODES) return;
    int s0 = d_row[gw], s1 = d_row[gw + 1];
    const float2* pl2 = (const float2*)d_pl;
    float a0 = 0.f, a1 = 0.f;
    for (int base = s0; base < s1; base += 32) {
        int rem = s1 - base;
        int sv = (lane < rem) ? d_csr[base + lane] : 0;
        int cnt = rem < 32 ? rem : 32;
        int j = 0;
        for (; j + 4 <= cnt; j += 4) {
            int sa = __shfl_sync(0xffffffffu, sv, j);
            int sb = __shfl_sync(0xffffffffu, sv, j + 1);
            int sc = __shfl_sync(0xffffffffu, sv, j + 2);
            int sd = __shfl_sync(0xffffffffu, sv, j + 3);
            float2 va = pl2[sa * 32 + lane];
            float2 vb = pl2[sb * 32 + lane];
            float2 vc = pl2[sc * 32 + lane];
            float2 vd = pl2[sd * 32 + lane];
            a0 += va.x + vb.x + vc.x + vd.x;
            a1 += va.y + vb.y + vc.y + vd.y;
        }
        for (; j < cnt; j++) {
            int s = __shfl_sync(0xffffffffu, sv, j);
            float2 v = pl2[s * 32 + lane];
            a0 += v.x; a1 += v.y;
        }
    }
    int deg = s1 - s0;
    float sc = 1.0f / (float)(deg > 1 ? deg : 1);
    float2 pr = ((const float2*)d_pr)[gw * 32 + lane];
    float2 bb = ((const float2*)b2)[lane];
    float h0 = fmaxf(a0 * sc + pr.x + bb.x, 0.f);
    float h1 = fmaxf(a1 * sc + pr.y + bb.y, 0.f);
    float2 w0 = ((const float2*)Wfc)[lane];
    float2 w1 = ((const float2*)Wfc)[32 + lane];
    float o0 = h0 * w0.x + h1 * w0.y;
    float o1 = h0 * w1.x + h1 * w1.y;
    #pragma unroll
    for (int o = 16; o; o >>= 1) {
        o0 += __shfl_xor_sync(0xffffffffu, o0, o);
        o1 += __shfl_xor_sync(0xffffffffu, o1, o);
    }
    if (lane == 0) {
        out[2 * gw]     = o0 + bfc[0];
        out[2 * gw + 1] = o1 + bfc[1];
    }
}

// ---------------- launch ----------------
extern "C" void kernel_launch(void* const* d_in, const int* in_sizes, int n_in,
                              void* d_out, int out_size) {
    const float* x   = (const float*)d_in[0];
    const int*   ei  = (const int*)d_in[1];
    const float* W1l = (const float*)d_in[2];
    const float* b1  = (const float*)d_in[3];
    const float* W1r = (const float*)d_in[4];
    const float* W2l = (const float*)d_in[5];
    const float* b2  = (const float*)d_in[6];
    const float* W2r = (const float*)d_in[7];
    const float* Wfc = (const float*)d_in[8];
    const float* bfc = (const float*)d_in[9];
    float* out = (float*)d_out;
    const int* src = ei;
    const int* dst = ei + EDGES;

    const int SMEM_F = (32768 + 16384 + 2 * 4096) * 4;   // 229,376 B
    cudaFuncSetAttribute(k_fused, cudaFuncAttributeMaxDynamicSharedMemorySize, SMEM_F);

    k_zero<<<(NODES + 255) / 256, 256>>>();
    k_wt<<<(256 * 128 + 255) / 256, 256>>>(W1l, W1r, W2l, W2r);
    k_hist<<<(EDGES + 255) / 256, 256>>>(dst);
    k_scan1<<<NCHUNK, CHUNK>>>();
    k_scan2<<<1, 128>>>();
    k_scan3<<<(NODES + 255) / 256, 256>>>();
    k_scatter<<<(EDGES + 255) / 256, 256>>>(src, dst);
    k_agg1<<<(NODES * 32 + 255) / 256, 256>>>(x);
    k_fused<<<148, 256, SMEM_F>>>(x, b1);
    k_agg2fc<<<(NODES * 32 + 255) / 256, 256>>>(b2, Wfc, bfc, out);
}

// round 5
// speedup vs baseline: 1.0746x; 1.0746x over previous
#include <cuda_runtime.h>
#include <cstdint>

#define NODES 100000
#define EDGES 1600000
#define TILES 782            // 782 * 128 = 100096
#define NPAD  100096
#define CHUNK 1024
#define NCHUNK 98

// ---------------- scratch (device globals; no allocation) ----------------
__device__ int   d_deg[NODES];
__device__ int   d_cursor[NODES];
__device__ int   d_row[NODES + 1];   // per-chunk exclusive scan (+ csums at read time)
__device__ int   d_csr[EDGES];
__device__ int   d_csums[NCHUNK];
__device__ float d_mean1[NPAD * 128];   // mean-aggregated x (padded rows stay 0)
__device__ float d_h1[NPAD * 128];      // layer1 output
__device__ float d_pl[NPAD * 64];       // h1 @ W2l^T (to be aggregated)
__device__ float d_pr[NPAD * 64];       // h1 @ W2r^T (self term)
__device__ float d_wt1[256 * 128];      // transposed [W1l; W1r]  (k-major)
__device__ float d_wt2[128 * 128];      // transposed [W2l | W2r] (k-major)

// ---------------- helpers ----------------
__device__ __forceinline__ uint32_t f2tf(float f) {
    uint32_t u; asm("cvt.rna.tf32.f32 %0, %1;" : "=r"(u) : "f"(f)); return u;
}

__device__ __forceinline__ void mma8(float* d, const uint32_t* a, uint2 b) {
    asm volatile(
        "mma.sync.aligned.m16n8k8.row.col.f32.tf32.tf32.f32 "
        "{%0,%1,%2,%3}, {%4,%5,%6,%7}, {%8,%9}, {%0,%1,%2,%3};\n"
        : "+f"(d[0]), "+f"(d[1]), "+f"(d[2]), "+f"(d[3])
        : "r"(a[0]), "r"(a[1]), "r"(a[2]), "r"(a[3]), "r"(b.x), "r"(b.y));
}

// ---------------- init: zero counters + weight pre-transpose ----------------
__global__ void k_init(const float* __restrict__ W1l, const float* __restrict__ W1r,
                       const float* __restrict__ W2l, const float* __restrict__ W2r) {
    int i = blockIdx.x * blockDim.x + threadIdx.x;
    if (i < NODES) { d_deg[i] = 0; d_cursor[i] = 0; }
    if (i < 256 * 128) {
        int k = i >> 7, n = i & 127;
        d_wt1[i] = (k < 128) ? W1l[n * 128 + k] : W1r[n * 128 + (k - 128)];
    }
    if (i < 128 * 128) {
        int k = i >> 7, n = i & 127;
        d_wt2[i] = (n < 64) ? W2l[n * 128 + k] : W2r[(n - 64) * 128 + k];
    }
}

// ---------------- CSR build ----------------
__global__ void k_hist(const int* __restrict__ dst) {
    int i = blockIdx.x * blockDim.x + threadIdx.x;
    if (i < EDGES) atomicAdd(&d_deg[dst[i]], 1);
}

__global__ void k_scan1() {
    __shared__ int ws[32];
    int i = blockIdx.x * CHUNK + threadIdx.x;
    int lane = threadIdx.x & 31, wid = threadIdx.x >> 5;
    int v = (i < NODES) ? d_deg[i] : 0;
    int x = v;
    #pragma unroll
    for (int o = 1; o < 32; o <<= 1) {
        int y = __shfl_up_sync(0xffffffffu, x, o);
        if (lane >= o) x += y;
    }
    if (lane == 31) ws[wid] = x;
    __syncthreads();
    if (wid == 0) {
        int s = ws[lane];
        #pragma unroll
        for (int o = 1; o < 32; o <<= 1) {
            int y = __shfl_up_sync(0xffffffffu, s, o);
            if (lane >= o) s += y;
        }
        ws[lane] = s;
    }
    __syncthreads();
    int incl = x + (wid > 0 ? ws[wid - 1] : 0);
    if (i <= NODES) d_row[i] = incl - v;    // exclusive within chunk (incl. i==NODES)
    if (threadIdx.x == CHUNK - 1) d_csums[blockIdx.x] = incl;
}

__global__ void k_scan2() {   // 128-thread parallel exclusive scan over NCHUNK
    __shared__ int ws[4];
    int t = threadIdx.x, lane = t & 31, w = t >> 5;
    int v = (t < NCHUNK) ? d_csums[t] : 0;
    int xx = v;
    #pragma unroll
    for (int o = 1; o < 32; o <<= 1) {
        int y = __shfl_up_sync(0xffffffffu, xx, o);
        if (lane >= o) xx += y;
    }
    if (lane == 31) ws[w] = xx;
    __syncthreads();
    int add = 0;
    #pragma unroll
    for (int i = 0; i < 4; i++) add += (i < w) ? ws[i] : 0;
    if (t < NCHUNK) d_csums[t] = xx + add - v;
}

__global__ void k_scatter(const int* __restrict__ src, const int* __restrict__ dst) {
    int i = blockIdx.x * blockDim.x + threadIdx.x;
    if (i < EDGES) {
        int d = dst[i];
        int o = atomicAdd(&d_cursor[d], 1);
        d_csr[d_row[d] + d_csums[d >> 10] + o] = src[i];
    }
}

// ---------------- layer1 aggregation: warp per node ----------------
__global__ void __launch_bounds__(256) k_agg1(const float* __restrict__ x) {
    int gw = (blockIdx.x * blockDim.x + threadIdx.x) >> 5;
    int lane = threadIdx.x & 31;
    if (gw >= NODES) return;
    int s0 = d_row[gw] + d_csums[gw >> 10];
    int s1 = d_row[gw + 1] + d_csums[(gw + 1) >> 10];
    const float4* x4 = (const float4*)x;
    float4 acc = make_float4(0.f, 0.f, 0.f, 0.f);
    for (int base = s0; base < s1; base += 32) {
        int rem = s1 - base;
        int sv = (lane < rem) ? d_csr[base + lane] : 0;
        int cnt = rem < 32 ? rem : 32;
        int j = 0;
        for (; j + 4 <= cnt; j += 4) {
            int sa = __shfl_sync(0xffffffffu, sv, j);
            int sb = __shfl_sync(0xffffffffu, sv, j + 1);
            int sc = __shfl_sync(0xffffffffu, sv, j + 2);
            int sd = __shfl_sync(0xffffffffu, sv, j + 3);
            float4 va = x4[sa * 32 + lane];
            float4 vb = x4[sb * 32 + lane];
            float4 vc = x4[sc * 32 + lane];
            float4 vd = x4[sd * 32 + lane];
            acc.x += va.x + vb.x + vc.x + vd.x;
            acc.y += va.y + vb.y + vc.y + vd.y;
            acc.z += va.z + vb.z + vc.z + vd.z;
            acc.w += va.w + vb.w + vc.w + vd.w;
        }
        for (; j < cnt; j++) {
            int s = __shfl_sync(0xffffffffu, sv, j);
            float4 v = x4[s * 32 + lane];
            acc.x += v.x; acc.y += v.y; acc.z += v.z; acc.w += v.w;
        }
    }
    int deg = s1 - s0;
    float sc = 1.0f / (float)(deg > 1 ? deg : 1);
    float4 m = make_float4(acc.x * sc, acc.y * sc, acc.z * sc, acc.w * sc);
    ((float4*)d_mean1)[gw * 32 + lane] = m;
}

// ---------------- TF32 tensor-core GEMMs ----------------
// Tile: 128 nodes x 128 outs per block, 256 threads = 8 warps (4x2),
// warp tile 32x64 = 2 m-frags x 8 n-frags of m16n8k8.
// B resident in smem, paired layout Bp[ks][n][lk][2] for LDS.64 frag loads.
// A double-buffered in 32-wide K chunks, PAIRED layout Ab[buf][ks][row][8]
// with within-group k permutation kp = (k&3)*2 + (k>>2), so each A fragment
// is two LDS.64: lo = {A[g,t], A[g,t+4]}, hi = {A[g+8,t], A[g+8,t+4]}.

extern __shared__ uint32_t smu[];

// GEMM1: h1 = relu([mean1 | x] @ wt1 + b1), K=256 (8 chunks)
__global__ void __launch_bounds__(256) k_gemm1(const float* __restrict__ x,
                                               const float* __restrict__ b1) {
    uint32_t* Bp = smu;              // 32768 words (128 KB)
    uint32_t* Ab = smu + 32768;      // 2 * 4096 words (32 KB)
    int tid = threadIdx.x, lane = tid & 31, w = tid >> 5;
    int wr = w >> 1, wc = w & 1;
    int g = lane >> 2, t = lane & 3;

    for (int i = tid; i < 32768; i += 256) {
        int k = i >> 7, n = i & 127;
        int ks = k >> 3, r = k & 7, half = r >> 2, lk = r & 3;
        Bp[((ks * 128 + n) << 3) + (lk << 1) + half] = f2tf(d_wt1[i]);
    }
    __syncthreads();

    int arow = tid >> 1;             // 0..127
    int acol0 = (tid & 1) << 4;      // 0 or 16

    float bx[8], by[8];
    #pragma unroll
    for (int nf = 0; nf < 8; nf++) {
        int cc = wc * 64 + nf * 8 + 2 * t;
        bx[nf] = b1[cc]; by[nf] = b1[cc + 1];
    }

    for (int tile = blockIdx.x; tile < TILES; tile += gridDim.x) {
        int nb = tile << 7;
        float acc[2][8][4];
        #pragma unroll
        for (int mf = 0; mf < 2; mf++)
            #pragma unroll
            for (int nf = 0; nf < 8; nf++)
                #pragma unroll
                for (int q = 0; q < 4; q++) acc[mf][nf][q] = 0.f;

        float4 r4[4];
        auto ldgch = [&](int c) {
            int node = nb + arow;
            const float* src;
            if (c < 4) src = d_mean1 + (size_t)node * 128 + c * 32 + acol0;
            else {
                int nc = node < NODES ? node : NODES - 1;
                src = x + (size_t)nc * 128 + (c - 4) * 32 + acol0;
            }
            #pragma unroll
            for (int i = 0; i < 4; i++) r4[i] = *(const float4*)(src + 4 * i);
        };
        auto stsch = [&](int buf) {
            // r4[0],r4[1] = k-group (acol0>>3); r4[2],r4[3] = next group.
            // paired positions: (k, k+4) -> words (2k, 2k+1), k in 0..3
            uint32_t* p0 = Ab + buf * 4096 + (acol0 >> 3) * 1024 + arow * 8;
            uint32_t* p1 = p0 + 1024;
            *(uint2*)(p0 + 0) = make_uint2(f2tf(r4[0].x), f2tf(r4[1].x));
            *(uint2*)(p0 + 2) = make_uint2(f2tf(r4[0].y), f2tf(r4[1].y));
            *(uint2*)(p0 + 4) = make_uint2(f2tf(r4[0].z), f2tf(r4[1].z));
            *(uint2*)(p0 + 6) = make_uint2(f2tf(r4[0].w), f2tf(r4[1].w));
            *(uint2*)(p1 + 0) = make_uint2(f2tf(r4[2].x), f2tf(r4[3].x));
            *(uint2*)(p1 + 2) = make_uint2(f2tf(r4[2].y), f2tf(r4[3].y));
            *(uint2*)(p1 + 4) = make_uint2(f2tf(r4[2].z), f2tf(r4[3].z));
            *(uint2*)(p1 + 6) = make_uint2(f2tf(r4[2].w), f2tf(r4[3].w));
        };

        ldgch(0);
        #pragma unroll 1
        for (int c = 0; c < 8; c++) {
            int buf = c & 1;
            stsch(buf);
            __syncthreads();
            if (c < 7) ldgch(c + 1);
            const uint32_t* abase0 = Ab + buf * 4096;
            #pragma unroll
            for (int ks = 0; ks < 4; ks++) {
                const uint32_t* ab = abase0 + ks * 1024;
                uint32_t a[2][4];
                #pragma unroll
                for (int mf = 0; mf < 2; mf++) {
                    int r0 = wr * 32 + mf * 16 + g;
                    uint2 lo = *(const uint2*)(ab + r0 * 8 + 2 * t);
                    uint2 hi = *(const uint2*)(ab + (r0 + 8) * 8 + 2 * t);
                    a[mf][0] = lo.x; a[mf][1] = hi.x;
                    a[mf][2] = lo.y; a[mf][3] = hi.y;
                }
                int ksg = c * 4 + ks;
                #pragma unroll
                for (int nf = 0; nf < 8; nf++) {
                    int n = wc * 64 + nf * 8 + g;
                    uint2 b = *(const uint2*)(Bp + ((ksg * 128 + n) << 3) + (t << 1));
                    mma8(acc[0][nf], a[0], b);
                    mma8(acc[1][nf], a[1], b);
                }
            }
        }

        #pragma unroll
        for (int mf = 0; mf < 2; mf++) {
            int r0 = nb + wr * 32 + mf * 16 + g;
            #pragma unroll
            for (int nf = 0; nf < 8; nf++) {
                int cc = wc * 64 + nf * 8 + 2 * t;
                float2 v0, v1;
                v0.x = fmaxf(acc[mf][nf][0] + bx[nf], 0.f);
                v0.y = fmaxf(acc[mf][nf][1] + by[nf], 0.f);
                v1.x = fmaxf(acc[mf][nf][2] + bx[nf], 0.f);
                v1.y = fmaxf(acc[mf][nf][3] + by[nf], 0.f);
                *(float2*)(d_h1 + (size_t)r0 * 128 + cc) = v0;
                *(float2*)(d_h1 + (size_t)(r0 + 8) * 128 + cc) = v1;
            }
        }
        __syncthreads();
    }
}

// GEMM2: [pl | pr] = h1 @ wt2, K=128 (4 chunks)
__global__ void __launch_bounds__(256) k_gemm2() {
    uint32_t* Bp = smu;              // 16384 words (64 KB)
    uint32_t* Ab = smu + 16384;      // 2 * 4096 words (32 KB)
    int tid = threadIdx.x, lane = tid & 31, w = tid >> 5;
    int wr = w >> 1, wc = w & 1;
    int g = lane >> 2, t = lane & 3;

    for (int i = tid; i < 16384; i += 256) {
        int k = i >> 7, n = i & 127;
        int ks = k >> 3, r = k & 7, half = r >> 2, lk = r & 3;
        Bp[((ks * 128 + n) << 3) + (lk << 1) + half] = f2tf(d_wt2[i]);
    }
    __syncthreads();

    int arow = tid >> 1;
    int acol0 = (tid & 1) << 4;

    for (int tile = blockIdx.x; tile < TILES; tile += gridDim.x) {
        int nb = tile << 7;
        float acc[2][8][4];
        #pragma unroll
        for (int mf = 0; mf < 2; mf++)
            #pragma unroll
            for (int nf = 0; nf < 8; nf++)
                #pragma unroll
                for (int q = 0; q < 4; q++) acc[mf][nf][q] = 0.f;

        float4 r4[4];
        auto ldgch = [&](int c) {
            const float* src = d_h1 + (size_t)(nb + arow) * 128 + c * 32 + acol0;
            #pragma unroll
            for (int i = 0; i < 4; i++) r4[i] = *(const float4*)(src + 4 * i);
        };
        auto stsch = [&](int buf) {
            uint32_t* p0 = Ab + buf * 4096 + (acol0 >> 3) * 1024 + arow * 8;
            uint32_t* p1 = p0 + 1024;
            *(uint2*)(p0 + 0) = make_uint2(f2tf(r4[0].x), f2tf(r4[1].x));
            *(uint2*)(p0 + 2) = make_uint2(f2tf(r4[0].y), f2tf(r4[1].y));
            *(uint2*)(p0 + 4) = make_uint2(f2tf(r4[0].z), f2tf(r4[1].z));
            *(uint2*)(p0 + 6) = make_uint2(f2tf(r4[0].w), f2tf(r4[1].w));
            *(uint2*)(p1 + 0) = make_uint2(f2tf(r4[2].x), f2tf(r4[3].x));
            *(uint2*)(p1 + 2) = make_uint2(f2tf(r4[2].y), f2tf(r4[3].y));
            *(uint2*)(p1 + 4) = make_uint2(f2tf(r4[2].z), f2tf(r4[3].z));
            *(uint2*)(p1 + 6) = make_uint2(f2tf(r4[2].w), f2tf(r4[3].w));
        };

        ldgch(0);
        #pragma unroll 1
        for (int c = 0; c < 4; c++) {
            int buf = c & 1;
            stsch(buf);
            __syncthreads();
            if (c < 3) ldgch(c + 1);
            const uint32_t* abase0 = Ab + buf * 4096;
            #pragma unroll
            for (int ks = 0; ks < 4; ks++) {
                const uint32_t* ab = abase0 + ks * 1024;
                uint32_t a[2][4];
                #pragma unroll
                for (int mf = 0; mf < 2; mf++) {
                    int r0 = wr * 32 + mf * 16 + g;
                    uint2 lo = *(const uint2*)(ab + r0 * 8 + 2 * t);
                    uint2 hi = *(const uint2*)(ab + (r0 + 8) * 8 + 2 * t);
                    a[mf][0] = lo.x; a[mf][1] = hi.x;
                    a[mf][2] = lo.y; a[mf][3] = hi.y;
                }
                int ksg = c * 4 + ks;
                #pragma unroll
                for (int nf = 0; nf < 8; nf++) {
                    int n = wc * 64 + nf * 8 + g;
                    uint2 b = *(const uint2*)(Bp + ((ksg * 128 + n) << 3) + (t << 1));
                    mma8(acc[0][nf], a[0], b);
                    mma8(acc[1][nf], a[1], b);
                }
            }
        }

        #pragma unroll
        for (int mf = 0; mf < 2; mf++) {
            int r0 = nb + wr * 32 + mf * 16 + g;
            #pragma unroll
            for (int nf = 0; nf < 8; nf++) {
                int cc = wc * 64 + nf * 8 + 2 * t;
                float2 v0 = { acc[mf][nf][0], acc[mf][nf][1] };
                float2 v1 = { acc[mf][nf][2], acc[mf][nf][3] };
                if (wc == 0) {
                    *(float2*)(d_pl + (size_t)r0 * 64 + cc) = v0;
                    *(float2*)(d_pl + (size_t)(r0 + 8) * 64 + cc) = v1;
                } else {
                    *(float2*)(d_pr + (size_t)r0 * 64 + (cc - 64)) = v0;
                    *(float2*)(d_pr + (size_t)(r0 + 8) * 64 + (cc - 64)) = v1;
                }
            }
        }
        __syncthreads();
    }
}

// ---------------- layer2 aggregation + bias + relu + FC, fused ----------------
__global__ void __launch_bounds__(256) k_agg2fc(const float* __restrict__ b2,
                                                const float* __restrict__ Wfc,
                                                const float* __restrict__ bfc,
                                                float* __restrict__ out) {
    int gw = (blockIdx.x * blockDim.x + threadIdx.x) >> 5;
    int lane = threadIdx.x & 31;
    if (gw >= NODES) return;
    int s0 = d_row[gw] + d_csums[gw >> 10];
    int s1 = d_row[gw + 1] + d_csums[(gw + 1) >> 10];
    const float2* pl2 = (const float2*)d_pl;
    float a0 = 0.f, a1 = 0.f;
    for (int base = s0; base < s1; base += 32) {
        int rem = s1 - base;
        int sv = (lane < rem) ? d_csr[base + lane] : 0;
        int cnt = rem < 32 ? rem : 32;
        int j = 0;
        for (; j + 4 <= cnt; j += 4) {
            int sa = __shfl_sync(0xffffffffu, sv, j);
            int sb = __shfl_sync(0xffffffffu, sv, j + 1);
            int sc = __shfl_sync(0xffffffffu, sv, j + 2);
            int sd = __shfl_sync(0xffffffffu, sv, j + 3);
            float2 va = pl2[sa * 32 + lane];
            float2 vb = pl2[sb * 32 + lane];
            float2 vc = pl2[sc * 32 + lane];
            float2 vd = pl2[sd * 32 + lane];
            a0 += va.x + vb.x + vc.x + vd.x;
            a1 += va.y + vb.y + vc.y + vd.y;
        }
        for (; j < cnt; j++) {
            int s = __shfl_sync(0xffffffffu, sv, j);
            float2 v = pl2[s * 32 + lane];
            a0 += v.x; a1 += v.y;
        }
    }
    int deg = s1 - s0;
    float sc = 1.0f / (float)(deg > 1 ? deg : 1);
    float2 pr = ((const float2*)d_pr)[gw * 32 + lane];
    float2 bb = ((const float2*)b2)[lane];
    float h0 = fmaxf(a0 * sc + pr.x + bb.x, 0.f);
    float h1 = fmaxf(a1 * sc + pr.y + bb.y, 0.f);
    float2 w0 = ((const float2*)Wfc)[lane];
    float2 w1 = ((const float2*)Wfc)[32 + lane];
    float o0 = h0 * w0.x + h1 * w0.y;
    float o1 = h0 * w1.x + h1 * w1.y;
    #pragma unroll
    for (int o = 16; o; o >>= 1) {
        o0 += __shfl_xor_sync(0xffffffffu, o0, o);
        o1 += __shfl_xor_sync(0xffffffffu, o1, o);
    }
    if (lane == 0) {
        out[2 * gw]     = o0 + bfc[0];
        out[2 * gw + 1] = o1 + bfc[1];
    }
}

// ---------------- launch ----------------
extern "C" void kernel_launch(void* const* d_in, const int* in_sizes, int n_in,
                              void* d_out, int out_size) {
    const float* x   = (const float*)d_in[0];
    const int*   ei  = (const int*)d_in[1];
    const float* W1l = (const float*)d_in[2];
    const float* b1  = (const float*)d_in[3];
    const float* W1r = (const float*)d_in[4];
    const float* W2l = (const float*)d_in[5];
    const float* b2  = (const float*)d_in[6];
    const float* W2r = (const float*)d_in[7];
    const float* Wfc = (const float*)d_in[8];
    const float* bfc = (const float*)d_in[9];
    float* out = (float*)d_out;
    const int* src = ei;
    const int* dst = ei + EDGES;

    const int SMEM_G1 = (32768 + 2 * 4096) * 4;   // 163,840 B
    const int SMEM_G2 = (16384 + 2 * 4096) * 4;   //  98,304 B
    cudaFuncSetAttribute(k_gemm1, cudaFuncAttributeMaxDynamicSharedMemorySize, SMEM_G1);
    cudaFuncSetAttribute(k_gemm2, cudaFuncAttributeMaxDynamicSharedMemorySize, SMEM_G2);

    k_init<<<(NODES + 255) / 256, 256>>>(W1l, W1r, W2l, W2r);
    k_hist<<<(EDGES + 255) / 256, 256>>>(dst);
    k_scan1<<<NCHUNK, CHUNK>>>();
    k_scan2<<<1, 128>>>();
    k_scatter<<<(EDGES + 255) / 256, 256>>>(src, dst);
    k_agg1<<<(NODES * 32 + 255) / 256, 256>>>(x);
    k_gemm1<<<148, 256, SMEM_G1>>>(x, b1);
    k_gemm2<<<148, 256, SMEM_G2>>>();
    k_agg2fc<<<(NODES * 32 + 255) / 256, 256>>>(b2, Wfc, bfc, out);
}

// round 6
// speedup vs baseline: 1.5067x; 1.4021x over previous
#include <cuda_runtime.h>
#include <cuda_fp16.h>
#include <cstdint>

#define NODES 100000
#define EDGES 1600000
#define TILES 782            // 782 * 128 = 100096
#define NPAD  100096
#define CHUNK 1024
#define NCHUNK 98

// ---------------- scratch (device globals; no allocation) ----------------
__device__ int   d_deg[NODES];
__device__ int   d_cursor[NODES];
__device__ int   d_row[NODES + 1];   // per-chunk exclusive scan (+ csums at read)
__device__ int   d_csr[EDGES];
__device__ int   d_csums[NCHUNK];
__device__ uint2 d_xh[NODES * 32];      // x in fp16 (128 halfs/row)
__device__ uint2 d_mean1h[NPAD * 32];   // mean-aggregated x, fp16
__device__ uint32_t d_h1h[NPAD * 64];   // layer1 output, fp16
__device__ uint32_t d_plh[NPAD * 32];   // h1 @ W2l^T, fp16
__device__ uint32_t d_prh[NPAD * 32];   // h1 @ W2r^T, fp16
__device__ uint32_t d_wt1p[16384];      // [W1l;W1r] pre-packed smem fragment layout
__device__ uint32_t d_wt2p[8192];       // [W2l|W2r] pre-packed

// ---------------- helpers ----------------
__device__ __forceinline__ uint32_t packh2(float a, float b) {
    half2 h = __floats2half2_rn(a, b);
    return *(uint32_t*)&h;
}
__device__ __forceinline__ float2 unph2(uint32_t u) {
    return __half22float2(*(half2*)&u);
}

__device__ __forceinline__ void mmah(float* d, const uint32_t* a, uint2 b) {
    asm volatile(
        "mma.sync.aligned.m16n8k16.row.col.f32.f16.f16.f32 "
        "{%0,%1,%2,%3}, {%4,%5,%6,%7}, {%8,%9}, {%0,%1,%2,%3};\n"
        : "+f"(d[0]), "+f"(d[1]), "+f"(d[2]), "+f"(d[3])
        : "r"(a[0]), "r"(a[1]), "r"(a[2]), "r"(a[3]), "r"(b.x), "r"(b.y));
}

// weight element accessors (virtual concatenated matrices)
__device__ __forceinline__ float wt1_at(const float* W1l, const float* W1r, int n, int k) {
    return (k < 128) ? W1l[n * 128 + k] : W1r[n * 128 + (k - 128)];
}
__device__ __forceinline__ float wt2_at(const float* W2l, const float* W2r, int n, int k) {
    return (n < 64) ? W2l[n * 128 + k] : W2r[(n - 64) * 128 + k];
}

// ---------------- init: zero counters + x->fp16 + weight pre-pack ----------------
__global__ void k_init(const float* __restrict__ x,
                       const float* __restrict__ W1l, const float* __restrict__ W1r,
                       const float* __restrict__ W2l, const float* __restrict__ W2r) {
    int i = blockIdx.x * blockDim.x + threadIdx.x;
    if (i < NODES) { d_deg[i] = 0; d_cursor[i] = 0; }
    if (i < NODES * 32) {            // 3.2M: 4 floats each
        float4 v = ((const float4*)x)[i];
        d_xh[i] = make_uint2(packh2(v.x, v.y), packh2(v.z, v.w));
    }
    // B fragment layout: uint index ((ks*128+n)*8 + w); w even -> halves(2p,2p+1),
    // w odd -> halves(2p+8, 2p+9), p = w>>1, k = ks*16 + that.
    if (i < 16384) {
        int w = i & 7, n = (i >> 3) & 127, ks = i >> 10;
        int p = w >> 1;
        int kb = (w & 1) ? (2 * p + 8) : (2 * p);
        int k = ks * 16 + kb;
        d_wt1p[i] = packh2(wt1_at(W1l, W1r, n, k), wt1_at(W1l, W1r, n, k + 1));
    }
    if (i < 8192) {
        int w = i & 7, n = (i >> 3) & 127, ks = i >> 10;
        int p = w >> 1;
        int kb = (w & 1) ? (2 * p + 8) : (2 * p);
        int k = ks * 16 + kb;
        d_wt2p[i] = packh2(wt2_at(W2l, W2r, n, k), wt2_at(W2l, W2r, n, k + 1));
    }
}

// ---------------- CSR build ----------------
__global__ void k_hist(const int* __restrict__ dst) {
    int i = blockIdx.x * blockDim.x + threadIdx.x;
    if (i < EDGES) atomicAdd(&d_deg[dst[i]], 1);
}

__global__ void k_scan1() {
    __shared__ int ws[32];
    int i = blockIdx.x * CHUNK + threadIdx.x;
    int lane = threadIdx.x & 31, wid = threadIdx.x >> 5;
    int v = (i < NODES) ? d_deg[i] : 0;
    int x = v;
    #pragma unroll
    for (int o = 1; o < 32; o <<= 1) {
        int y = __shfl_up_sync(0xffffffffu, x, o);
        if (lane >= o) x += y;
    }
    if (lane == 31) ws[wid] = x;
    __syncthreads();
    if (wid == 0) {
        int s = ws[lane];
        #pragma unroll
        for (int o = 1; o < 32; o <<= 1) {
            int y = __shfl_up_sync(0xffffffffu, s, o);
            if (lane >= o) s += y;
        }
        ws[lane] = s;
    }
    __syncthreads();
    int incl = x + (wid > 0 ? ws[wid - 1] : 0);
    if (i <= NODES) d_row[i] = incl - v;
    if (threadIdx.x == CHUNK - 1) d_csums[blockIdx.x] = incl;
}

__global__ void k_scan2() {
    __shared__ int ws[4];
    int t = threadIdx.x, lane = t & 31, w = t >> 5;
    int v = (t < NCHUNK) ? d_csums[t] : 0;
    int xx = v;
    #pragma unroll
    for (int o = 1; o < 32; o <<= 1) {
        int y = __shfl_up_sync(0xffffffffu, xx, o);
        if (lane >= o) xx += y;
    }
    if (lane == 31) ws[w] = xx;
    __syncthreads();
    int add = 0;
    #pragma unroll
    for (int i = 0; i < 4; i++) add += (i < w) ? ws[i] : 0;
    if (t < NCHUNK) d_csums[t] = xx + add - v;
}

__global__ void k_scatter(const int* __restrict__ src, const int* __restrict__ dst) {
    int i = blockIdx.x * blockDim.x + threadIdx.x;
    if (i < EDGES) {
        int d = dst[i];
        int o = atomicAdd(&d_cursor[d], 1);
        d_csr[d_row[d] + d_csums[d >> 10] + o] = src[i];
    }
}

// ---------------- layer1 aggregation: warp per node, fp16 gather ----------------
__global__ void __launch_bounds__(256) k_agg1() {
    int gw = (blockIdx.x * blockDim.x + threadIdx.x) >> 5;
    int lane = threadIdx.x & 31;
    if (gw >= NODES) return;
    int s0 = d_row[gw] + d_csums[gw >> 10];
    int s1 = d_row[gw + 1] + d_csums[(gw + 1) >> 10];
    float4 acc = make_float4(0.f, 0.f, 0.f, 0.f);
    for (int base = s0; base < s1; base += 32) {
        int rem = s1 - base;
        int sv = (lane < rem) ? d_csr[base + lane] : 0;
        int cnt = rem < 32 ? rem : 32;
        int j = 0;
        for (; j + 4 <= cnt; j += 4) {
            int sa = __shfl_sync(0xffffffffu, sv, j);
            int sb = __shfl_sync(0xffffffffu, sv, j + 1);
            int sc = __shfl_sync(0xffffffffu, sv, j + 2);
            int sd = __shfl_sync(0xffffffffu, sv, j + 3);
            uint2 va = d_xh[sa * 32 + lane];
            uint2 vb = d_xh[sb * 32 + lane];
            uint2 vc = d_xh[sc * 32 + lane];
            uint2 vd = d_xh[sd * 32 + lane];
            float2 a0 = unph2(va.x), a1 = unph2(va.y);
            float2 b0 = unph2(vb.x), b1 = unph2(vb.y);
            float2 c0 = unph2(vc.x), c1 = unph2(vc.y);
            float2 e0 = unph2(vd.x), e1 = unph2(vd.y);
            acc.x += a0.x + b0.x + c0.x + e0.x;
            acc.y += a0.y + b0.y + c0.y + e0.y;
            acc.z += a1.x + b1.x + c1.x + e1.x;
            acc.w += a1.y + b1.y + c1.y + e1.y;
        }
        for (; j < cnt; j++) {
            int s = __shfl_sync(0xffffffffu, sv, j);
            uint2 v = d_xh[s * 32 + lane];
            float2 p0 = unph2(v.x), p1 = unph2(v.y);
            acc.x += p0.x; acc.y += p0.y; acc.z += p1.x; acc.w += p1.y;
        }
    }
    int deg = s1 - s0;
    float sc = 1.0f / (float)(deg > 1 ? deg : 1);
    d_mean1h[gw * 32 + lane] =
        make_uint2(packh2(acc.x * sc, acc.y * sc), packh2(acc.z * sc, acc.w * sc));
}

// ---------------- fp16 tensor-core GEMMs ----------------
// Tile 128x128, 256 threads = 8 warps (4x2), warp tile 32x64,
// m16n8k16 frags: A smem [row][20 uints] per 32-k chunk (words j=0..15 =
// half-pairs (2j,2j+1); stride 20 -> conflict-free LDS.32). B resident
// in fragment layout (see k_init).

extern __shared__ uint32_t smu[];

// GEMM1: h1 = relu([mean1 | x] @ wt1 + b1), K=256 (8 chunks of 32)
__global__ void __launch_bounds__(256) k_gemm1(const float* __restrict__ b1) {
    uint32_t* Bp = smu;              // 16384 words (64 KB)
    uint32_t* Ab = smu + 16384;      // 2 * 2560 words (20 KB)
    int tid = threadIdx.x, lane = tid & 31, w = tid >> 5;
    int wr = w >> 1, wc = w & 1;
    int g = lane >> 2, t = lane & 3;

    for (int i = tid; i < 4096; i += 256)
        ((uint4*)Bp)[i] = ((const uint4*)d_wt1p)[i];
    __syncthreads();

    int arow = tid >> 1;             // 0..127
    int side = tid & 1;              // 0/1 -> 8-uint half of the chunk row

    float bx[8], by[8];
    #pragma unroll
    for (int nf = 0; nf < 8; nf++) {
        int cc = wc * 64 + nf * 8 + 2 * t;
        bx[nf] = b1[cc]; by[nf] = b1[cc + 1];
    }

    for (int tile = blockIdx.x; tile < TILES; tile += gridDim.x) {
        int nb = tile << 7;
        float acc[2][8][4];
        #pragma unroll
        for (int mf = 0; mf < 2; mf++)
            #pragma unroll
            for (int nf = 0; nf < 8; nf++)
                #pragma unroll
                for (int q = 0; q < 4; q++) acc[mf][nf][q] = 0.f;

        uint4 rv[2];
        auto ldgch = [&](int c) {
            int node = nb + arow;
            const uint32_t* src;
            if (c < 4) src = (const uint32_t*)d_mean1h + (size_t)node * 64 + c * 16 + side * 8;
            else {
                int nc = node < NODES ? node : NODES - 1;
                src = (const uint32_t*)d_xh + (size_t)nc * 64 + (c - 4) * 16 + side * 8;
            }
            rv[0] = *(const uint4*)src;
            rv[1] = *(const uint4*)(src + 4);
        };
        auto stsch = [&](int buf) {
            uint32_t* p = Ab + buf * 2560 + arow * 20 + side * 8;
            *(uint4*)p = rv[0];
            *(uint4*)(p + 4) = rv[1];
        };

        ldgch(0);
        #pragma unroll 1
        for (int c = 0; c < 8; c++) {
            int buf = c & 1;
            stsch(buf);
            __syncthreads();
            if (c < 7) ldgch(c + 1);
            const uint32_t* ab0 = Ab + buf * 2560;
            #pragma unroll
            for (int ksub = 0; ksub < 2; ksub++) {
                uint32_t a[2][4];
                #pragma unroll
                for (int mf = 0; mf < 2; mf++) {
                    const uint32_t* base = ab0 + (wr * 32 + mf * 16 + g) * 20 + ksub * 8;
                    a[mf][0] = base[t];
                    a[mf][1] = base[160 + t];      // row +8 -> +8*20
                    a[mf][2] = base[t + 4];
                    a[mf][3] = base[160 + t + 4];
                }
                int ks16 = c * 2 + ksub;
                #pragma unroll
                for (int nf = 0; nf < 8; nf++) {
                    int n = wc * 64 + nf * 8 + g;
                    uint2 b = *(const uint2*)(Bp + ((ks16 * 128 + n) << 3) + (t << 1));
                    mmah(acc[0][nf], a[0], b);
                    mmah(acc[1][nf], a[1], b);
                }
            }
        }

        #pragma unroll
        for (int mf = 0; mf < 2; mf++) {
            int r0 = nb + wr * 32 + mf * 16 + g;
            #pragma unroll
            for (int nf = 0; nf < 8; nf++) {
                int cc = wc * 64 + nf * 8 + 2 * t;
                uint32_t v0 = packh2(fmaxf(acc[mf][nf][0] + bx[nf], 0.f),
                                     fmaxf(acc[mf][nf][1] + by[nf], 0.f));
                uint32_t v1 = packh2(fmaxf(acc[mf][nf][2] + bx[nf], 0.f),
                                     fmaxf(acc[mf][nf][3] + by[nf], 0.f));
                d_h1h[(size_t)r0 * 64 + (cc >> 1)] = v0;
                d_h1h[(size_t)(r0 + 8) * 64 + (cc >> 1)] = v1;
            }
        }
        __syncthreads();
    }
}

// GEMM2: [pl | pr] = h1 @ wt2, K=128 (4 chunks of 32)
__global__ void __launch_bounds__(256) k_gemm2() {
    uint32_t* Bp = smu;              // 8192 words (32 KB)
    uint32_t* Ab = smu + 8192;       // 2 * 2560 words (20 KB)
    int tid = threadIdx.x, lane = tid & 31, w = tid >> 5;
    int wr = w >> 1, wc = w & 1;
    int g = lane >> 2, t = lane & 3;

    for (int i = tid; i < 2048; i += 256)
        ((uint4*)Bp)[i] = ((const uint4*)d_wt2p)[i];
    __syncthreads();

    int arow = tid >> 1;
    int side = tid & 1;

    for (int tile = blockIdx.x; tile < TILES; tile += gridDim.x) {
        int nb = tile << 7;
        float acc[2][8][4];
        #pragma unroll
        for (int mf = 0; mf < 2; mf++)
            #pragma unroll
            for (int nf = 0; nf < 8; nf++)
                #pragma unroll
                for (int q = 0; q < 4; q++) acc[mf][nf][q] = 0.f;

        uint4 rv[2];
        auto ldgch = [&](int c) {
            const uint32_t* src = d_h1h + (size_t)(nb + arow) * 64 + c * 16 + side * 8;
            rv[0] = *(const uint4*)src;
            rv[1] = *(const uint4*)(src + 4);
        };
        auto stsch = [&](int buf) {
            uint32_t* p = Ab + buf * 2560 + arow * 20 + side * 8;
            *(uint4*)p = rv[0];
            *(uint4*)(p + 4) = rv[1];
        };

        ldgch(0);
        #pragma unroll 1
        for (int c = 0; c < 4; c++) {
            int buf = c & 1;
            stsch(buf);
            __syncthreads();
            if (c < 3) ldgch(c + 1);
            const uint32_t* ab0 = Ab + buf * 2560;
            #pragma unroll
            for (int ksub = 0; ksub < 2; ksub++) {
                uint32_t a[2][4];
                #pragma unroll
                for (int mf = 0; mf < 2; mf++) {
                    const uint32_t* base = ab0 + (wr * 32 + mf * 16 + g) * 20 + ksub * 8;
                    a[mf][0] = base[t];
                    a[mf][1] = base[160 + t];
                    a[mf][2] = base[t + 4];
                    a[mf][3] = base[160 + t + 4];
                }
                int ks16 = c * 2 + ksub;
                #pragma unroll
                for (int nf = 0; nf < 8; nf++) {
                    int n = wc * 64 + nf * 8 + g;
                    uint2 b = *(const uint2*)(Bp + ((ks16 * 128 + n) << 3) + (t << 1));
                    mmah(acc[0][nf], a[0], b);
                    mmah(acc[1][nf], a[1], b);
                }
            }
        }

        #pragma unroll
        for (int mf = 0; mf < 2; mf++) {
            int r0 = nb + wr * 32 + mf * 16 + g;
            #pragma unroll
            for (int nf = 0; nf < 8; nf++) {
                int cc = wc * 64 + nf * 8 + 2 * t;
                uint32_t v0 = packh2(acc[mf][nf][0], acc[mf][nf][1]);
                uint32_t v1 = packh2(acc[mf][nf][2], acc[mf][nf][3]);
                if (wc == 0) {
                    d_plh[(size_t)r0 * 32 + (cc >> 1)] = v0;
                    d_plh[(size_t)(r0 + 8) * 32 + (cc >> 1)] = v1;
                } else {
                    d_prh[(size_t)r0 * 32 + ((cc - 64) >> 1)] = v0;
                    d_prh[(size_t)(r0 + 8) * 32 + ((cc - 64) >> 1)] = v1;
                }
            }
        }
        __syncthreads();
    }
}

// ---------------- layer2 aggregation + bias + relu + FC, fused ----------------
__global__ void __launch_bounds__(256) k_agg2fc(const float* __restrict__ b2,
                                                const float* __restrict__ Wfc,
                                                const float* __restrict__ bfc,
                                                float* __restrict__ out) {
    int gw = (blockIdx.x * blockDim.x + threadIdx.x) >> 5;
    int lane = threadIdx.x & 31;
    if (gw >= NODES) return;
    int s0 = d_row[gw] + d_csums[gw >> 10];
    int s1 = d_row[gw + 1] + d_csums[(gw + 1) >> 10];
    float a0 = 0.f, a1 = 0.f;
    for (int base = s0; base < s1; base += 32) {
        int rem = s1 - base;
        int sv = (lane < rem) ? d_csr[base + lane] : 0;
        int cnt = rem < 32 ? rem : 32;
        int j = 0;
        for (; j + 4 <= cnt; j += 4) {
            int sa = __shfl_sync(0xffffffffu, sv, j);
            int sb = __shfl_sync(0xffffffffu, sv, j + 1);
            int sc = __shfl_sync(0xffffffffu, sv, j + 2);
            int sd = __shfl_sync(0xffffffffu, sv, j + 3);
            float2 va = unph2(d_plh[sa * 32 + lane]);
            float2 vb = unph2(d_plh[sb * 32 + lane]);
            float2 vc = unph2(d_plh[sc * 32 + lane]);
            float2 vd = unph2(d_plh[sd * 32 + lane]);
            a0 += va.x + vb.x + vc.x + vd.x;
            a1 += va.y + vb.y + vc.y + vd.y;
        }
        for (; j < cnt; j++) {
            int s = __shfl_sync(0xffffffffu, sv, j);
            float2 v = unph2(d_plh[s * 32 + lane]);
            a0 += v.x; a1 += v.y;
        }
    }
    int deg = s1 - s0;
    float sc = 1.0f / (float)(deg > 1 ? deg : 1);
    float2 pr = unph2(d_prh[gw * 32 + lane]);
    float2 bb = ((const float2*)b2)[lane];
    float h0 = fmaxf(a0 * sc + pr.x + bb.x, 0.f);
    float h1 = fmaxf(a1 * sc + pr.y + bb.y, 0.f);
    float2 w0 = ((const float2*)Wfc)[lane];
    float2 w1 = ((const float2*)Wfc)[32 + lane];
    float o0 = h0 * w0.x + h1 * w0.y;
    float o1 = h0 * w1.x + h1 * w1.y;
    #pragma unroll
    for (int o = 16; o; o >>= 1) {
        o0 += __shfl_xor_sync(0xffffffffu, o0, o);
        o1 += __shfl_xor_sync(0xffffffffu, o1, o);
    }
    if (lane == 0) {
        out[2 * gw]     = o0 + bfc[0];
        out[2 * gw + 1] = o1 + bfc[1];
    }
}

// ---------------- launch ----------------
extern "C" void kernel_launch(void* const* d_in, const int* in_sizes, int n_in,
                              void* d_out, int out_size) {
    const float* x   = (const float*)d_in[0];
    const int*   ei  = (const int*)d_in[1];
    const float* W1l = (const float*)d_in[2];
    const float* b1  = (const float*)d_in[3];
    const float* W1r = (const float*)d_in[4];
    const float* W2l = (const float*)d_in[5];
    const float* b2  = (const float*)d_in[6];
    const float* W2r = (const float*)d_in[7];
    const float* Wfc = (const float*)d_in[8];
    const float* bfc = (const float*)d_in[9];
    float* out = (float*)d_out;
    const int* src = ei;
    const int* dst = ei + EDGES;

    const int SMEM_G1 = (16384 + 2 * 2560) * 4;   // 86,016 B -> 2 CTAs/SM
    const int SMEM_G2 = (8192 + 2 * 2560) * 4;    // 53,248 B -> 4 CTAs/SM
    cudaFuncSetAttribute(k_gemm1, cudaFuncAttributeMaxDynamicSharedMemorySize, SMEM_G1);
    cudaFuncSetAttribute(k_gemm2, cudaFuncAttributeMaxDynamicSharedMemorySize, SMEM_G2);

    k_init<<<(NODES * 32 + 255) / 256, 256>>>(x, W1l, W1r, W2l, W2r);
    k_hist<<<(EDGES + 255) / 256, 256>>>(dst);
    k_scan1<<<NCHUNK, CHUNK>>>();
    k_scan2<<<1, 128>>>();
    k_scatter<<<(EDGES + 255) / 256, 256>>>(src, dst);
    k_agg1<<<(NODES * 32 + 255) / 256, 256>>>();
    k_gemm1<<<296, 256, SMEM_G1>>>(b1);
    k_gemm2<<<592, 256, SMEM_G2>>>();
    k_agg2fc<<<(NODES * 32 + 255) / 256, 256>>>(b2, Wfc, bfc, out);
}